// round 3
// baseline (speedup 1.0000x reference)
#include <cuda_runtime.h>

#define BB   256
#define TT   2048
#define QD   1024
#define AD   128
#define DCH  8
#define DKK  21
#define PLL  11
#define MROW 24   // taps 0..20, [21]=0 (pad), [22]=v, [23]=T_b
#define BPB  4    // batches per prep block

// Per-batch fused conv weights
__device__ float g_M[BB * AD * MROW];

typedef unsigned long long u64;

__device__ __forceinline__ float tanh_fast(float x) {
    float y;
    asm("tanh.approx.f32 %0, %1;" : "=f"(y) : "f"(x));
    return y;
}
__device__ __forceinline__ u64 pk(float lo, float hi) {
    u64 r; asm("mov.b64 %0, {%1, %2};" : "=l"(r) : "f"(lo), "f"(hi)); return r;
}
__device__ __forceinline__ u64 fma2(u64 a, u64 b, u64 c) {
    u64 d; asm("fma.rn.f32x2 %0, %1, %2, %3;" : "=l"(d) : "l"(a), "l"(b), "l"(c)); return d;
}
__device__ __forceinline__ float2 unpk(u64 v) {
    float2 f; asm("mov.b64 {%0, %1}, %2;" : "=f"(f.x), "=f"(f.y) : "l"(v)); return f;
}

// ---------------------------------------------------------------------------
// Prep: 4 batches per block -> W matrix read 64x instead of 256x.
//   h = tanh(q@W^T + Wb); G_b = h@V^T; M_b = U@F + T@G_b
// ---------------------------------------------------------------------------
__global__ __launch_bounds__(128) void dca_prep_kernel(
    const float* __restrict__ query, const float* __restrict__ W_w,
    const float* __restrict__ W_b,   const float* __restrict__ V_w,
    const float* __restrict__ F_w,   const float* __restrict__ U_w,
    const float* __restrict__ T_w,   const float* __restrict__ T_b,
    const float* __restrict__ v_w)
{
    __shared__ float shq[BPB][QD];
    __shared__ float shh[BPB][AD];
    __shared__ float shG[BPB][DCH * DKK];
    const int b0 = blockIdx.x * BPB, tid = threadIdx.x;

    for (int i = tid; i < BPB * QD; i += 128)
        shq[i >> 10][i & (QD - 1)] = query[b0 * QD + i];
    __syncthreads();

    {   // stage 1: a = tid, all BPB batches per thread (W row read once)
        const int a = tid;
        const float4* wr = (const float4*)(W_w + a * QD);
        float acc[BPB];
#pragma unroll
        for (int bb = 0; bb < BPB; bb++) acc[bb] = 0.f;
#pragma unroll 8
        for (int j = 0; j < QD / 4; j++) {
            const float4 wv = wr[j];
#pragma unroll
            for (int bb = 0; bb < BPB; bb++) {
                const float4 qv = ((const float4*)shq[bb])[j];
                acc[bb] += wv.x * qv.x + wv.y * qv.y + wv.z * qv.z + wv.w * qv.w;
            }
        }
        const float wb = W_b[a];
#pragma unroll
        for (int bb = 0; bb < BPB; bb++) shh[bb][a] = tanhf(acc[bb] + wb);
    }
    __syncthreads();

    // stage 2: G_b[i] = dot(h_b, V_w[i,:])
    for (int i = tid; i < BPB * DCH * DKK; i += 128) {
        const int bb = i / (DCH * DKK), r = i - bb * (DCH * DKK);
        const float4* vr = (const float4*)(V_w + r * AD);
        const float4* hr = (const float4*)shh[bb];
        float acc = 0.f;
#pragma unroll
        for (int j = 0; j < AD / 4; j++) {
            const float4 vv = vr[j], hv = hr[j];
            acc += vv.x * hv.x + vv.y * hv.y + vv.z * hv.z + vv.w * hv.w;
        }
        shG[bb][r] = acc;
    }
    __syncthreads();

    // stage 3: M_b[a,k] = sum_c U[a,c]*F[c,k] + T[a,c]*G_b[c,k]
    for (int i = tid; i < BPB * AD * DKK; i += 128) {
        const int bb = i / (AD * DKK);
        const int rem = i - bb * (AD * DKK);
        const int a = rem / DKK, k = rem - a * DKK;
        float m = 0.f;
#pragma unroll
        for (int c = 0; c < DCH; c++)
            m += U_w[a * DCH + c] * F_w[c * DKK + k]
               + T_w[a * DCH + c] * shG[bb][c * DKK + k];
        g_M[(b0 + bb) * AD * MROW + a * MROW + k] = m;
    }
    for (int i = tid; i < BPB * AD; i += 128) {
        const int bb = i / AD, a = i - bb * AD;
        float* Mb = g_M + (b0 + bb) * AD * MROW + a * MROW;
        Mb[21] = 0.f; Mb[22] = v_w[a]; Mb[23] = T_b[a];
    }
}

// ---------------------------------------------------------------------------
// Main: one block per batch, each thread does 4 consecutive t.
// Tap-parity packed f32x2 math: packed acc lane0=even taps, lane1=odd taps.
// ---------------------------------------------------------------------------
__global__ __launch_bounds__(512) void dca_main_kernel(
    const float* __restrict__ alignment, const float* __restrict__ P,
    float* __restrict__ out)
{
    __shared__ float sal[TT + 32];
    __shared__ float sw[AD * MROW];
    __shared__ float sp[PLL];
    __shared__ float red[16];

    const int b = blockIdx.x, tid = threadIdx.x;

    for (int i = tid; i < TT; i += 512) sal[10 + i] = alignment[b * TT + i];
    if (tid < 10) sal[tid] = 0.f;
    if (tid < 22) sal[TT + 10 + tid] = 0.f;
    for (int i = tid; i < AD * MROW; i += 512) sw[i] = g_M[b * AD * MROW + i];
    if (tid < PLL) sp[tid] = P[tid];
    __syncthreads();

    const int t0 = tid * 4;
    float w[25];
#pragma unroll
    for (int k = 0; k < 25; k++) w[k] = sal[t0 + k];

    // packed window pairs
    u64 wA[12], wB[12];
#pragma unroll
    for (int j = 0; j < 12; j++) {
        wA[j] = pk(w[2 * j],     w[2 * j + 1]);
        wB[j] = pk(w[2 * j + 1], w[2 * j + 2]);
    }

    float e0 = 0.f, e1 = 0.f, e2 = 0.f, e3 = 0.f;

#pragma unroll 1
    for (int a = 0; a < AD; a++) {
        const u64* row = (const u64*)(sw + a * MROW);  // 11 m-pairs + (v,tb)
        u64 z0 = 0ull, z1 = 0ull, z2 = 0ull, z3 = 0ull;
#pragma unroll
        for (int j = 0; j < 11; j++) {
            const u64 m = row[j];
            z0 = fma2(m, wA[j],     z0);
            z1 = fma2(m, wB[j],     z1);
            z2 = fma2(m, wA[j + 1], z2);
            z3 = fma2(m, wB[j + 1], z3);
        }
        const float2 vt = unpk(row[11]);   // (v, tb)
        const float2 a0 = unpk(z0), a1 = unpk(z1), a2 = unpk(z2), a3 = unpk(z3);
        e0 += vt.x * tanh_fast(a0.x + a0.y + vt.y);
        e1 += vt.x * tanh_fast(a1.x + a1.y + vt.y);
        e2 += vt.x * tanh_fast(a2.x + a2.y + vt.y);
        e3 += vt.x * tanh_fast(a3.x + a3.y + vt.y);
    }

    // prior: p_j = log(clip(sum_{k<11} w[j+k]*P[k], 1e-6))
    {
        float s0 = 0.f, s1 = 0.f, s2 = 0.f, s3 = 0.f;
#pragma unroll
        for (int k = 0; k < PLL; k++) {
            const float pkk = sp[k];
            s0 += pkk * w[k];     s1 += pkk * w[k + 1];
            s2 += pkk * w[k + 2]; s3 += pkk * w[k + 3];
        }
        e0 += __logf(fmaxf(s0, 1e-6f));
        e1 += __logf(fmaxf(s1, 1e-6f));
        e2 += __logf(fmaxf(s2, 1e-6f));
        e3 += __logf(fmaxf(s3, 1e-6f));
    }

    const int lane = tid & 31, wid = tid >> 5;

    // block max
    float mx = fmaxf(fmaxf(e0, e1), fmaxf(e2, e3));
#pragma unroll
    for (int o = 16; o; o >>= 1) mx = fmaxf(mx, __shfl_xor_sync(~0u, mx, o));
    if (lane == 0) red[wid] = mx;
    __syncthreads();
    mx = red[0];
#pragma unroll
    for (int i = 1; i < 16; i++) mx = fmaxf(mx, red[i]);
    __syncthreads();

    // exp + block sum
    const float x0 = __expf(e0 - mx), x1 = __expf(e1 - mx);
    const float x2 = __expf(e2 - mx), x3 = __expf(e3 - mx);
    float sm = (x0 + x1) + (x2 + x3);
#pragma unroll
    for (int o = 16; o; o >>= 1) sm += __shfl_xor_sync(~0u, sm, o);
    if (lane == 0) red[wid] = sm;
    __syncthreads();
    sm = red[0];
#pragma unroll
    for (int i = 1; i < 16; i++) sm += red[i];

    const float inv = 1.0f / sm;
    float* o4 = out + b * TT + t0;
    o4[0] = x0 * inv; o4[1] = x1 * inv; o4[2] = x2 * inv; o4[3] = x3 * inv;
}

extern "C" void kernel_launch(void* const* d_in, const int* in_sizes, int n_in,
                              void* d_out, int out_size)
{
    const float* query     = (const float*)d_in[0];
    const float* alignment = (const float*)d_in[1];
    const float* P         = (const float*)d_in[2];
    const float* W_w       = (const float*)d_in[3];
    const float* W_b       = (const float*)d_in[4];
    const float* V_w       = (const float*)d_in[5];
    const float* F_w       = (const float*)d_in[6];
    const float* U_w       = (const float*)d_in[7];
    const float* T_w       = (const float*)d_in[8];
    const float* T_b       = (const float*)d_in[9];
    const float* v_w       = (const float*)d_in[10];
    float* out = (float*)d_out;

    dca_prep_kernel<<<BB / BPB, 128>>>(query, W_w, W_b, V_w, F_w, U_w, T_w, T_b, v_w);
    dca_main_kernel<<<BB, 512>>>(alignment, P, out);
}

// round 4
// speedup vs baseline: 1.2820x; 1.2820x over previous
#include <cuda_runtime.h>

#define BB   256
#define TT   2048
#define QD   1024
#define AD   128
#define DCH  8
#define DKK  21
#define PLL  11
#define MROW 24   // taps 0..20, [21]=v, [22]=T_b, [23]=pad
#define PB   2    // batches per prep block

// Per-batch fused conv weights
__device__ float g_M[BB * AD * MROW];

__device__ __forceinline__ float tanh_fast(float x) {
    float y;
    asm("tanh.approx.f32 %0, %1;" : "=f"(y) : "f"(x));
    return y;
}

__device__ __forceinline__ float warp_sum(float v) {
#pragma unroll
    for (int o = 16; o; o >>= 1) v += __shfl_xor_sync(~0u, v, o);
    return v;
}

// ---------------------------------------------------------------------------
// Prep: 2 batches per block, 128 blocks (~1 full wave), 256 threads.
// Stage 1 is warp-per-a-row: q in registers, W via coalesced float4 LDG,
// shfl-reduce. Then G = h@V^T and M = U@F + T@G for both batches.
// ---------------------------------------------------------------------------
__global__ __launch_bounds__(256) void dca_prep_kernel(
    const float* __restrict__ query, const float* __restrict__ W_w,
    const float* __restrict__ W_b,   const float* __restrict__ V_w,
    const float* __restrict__ F_w,   const float* __restrict__ U_w,
    const float* __restrict__ T_w,   const float* __restrict__ T_b,
    const float* __restrict__ v_w)
{
    __shared__ float shq[PB][QD];
    __shared__ float shh[PB][AD];
    __shared__ float shG[PB][DCH * DKK];

    const int b0 = blockIdx.x * PB, tid = threadIdx.x;
    const int lane = tid & 31, wrp = tid >> 5;   // 8 warps

    for (int i = tid; i < PB * QD; i += 256)
        shq[i >> 10][i & (QD - 1)] = query[b0 * QD + i];
    __syncthreads();

    // ---- stage 1: h[bb][a] = tanh(dot(q_bb, W_w[a,:]) + W_b[a]) ----
    {
        // q in registers: lane covers elements 4*lane + 128*j, j=0..7
        float4 q0[8], q1[8];
#pragma unroll
        for (int j = 0; j < 8; j++) {
            q0[j] = *(const float4*)&shq[0][4 * lane + 128 * j];
            q1[j] = *(const float4*)&shq[1][4 * lane + 128 * j];
        }
        // warp handles 16 a-rows
#pragma unroll 1
        for (int i = 0; i < 16; i++) {
            const int a = wrp * 16 + i;
            const float4* wr = (const float4*)(W_w + a * QD);
            float d0 = 0.f, d1 = 0.f;
#pragma unroll
            for (int j = 0; j < 8; j++) {
                const float4 wv = wr[lane + 32 * j];
                d0 += wv.x * q0[j].x + wv.y * q0[j].y + wv.z * q0[j].z + wv.w * q0[j].w;
                d1 += wv.x * q1[j].x + wv.y * q1[j].y + wv.z * q1[j].z + wv.w * q1[j].w;
            }
            d0 = warp_sum(d0);
            d1 = warp_sum(d1);
            if (lane == 0) {
                const float wb = W_b[a];
                shh[0][a] = tanhf(d0 + wb);
                shh[1][a] = tanhf(d1 + wb);
            }
        }
    }
    __syncthreads();

    // ---- stage 2: G[bb][r] = dot(h_bb, V_w[r,:]), r in [0,168) ----
    for (int i = tid; i < PB * DCH * DKK; i += 256) {
        const int bb = i / (DCH * DKK), r = i - bb * (DCH * DKK);
        const float4* vr = (const float4*)(V_w + r * AD);
        const float4* hr = (const float4*)shh[bb];
        float acc = 0.f;
#pragma unroll
        for (int j = 0; j < AD / 4; j++) {
            const float4 vv = vr[j], hv = hr[j];
            acc += vv.x * hv.x + vv.y * hv.y + vv.z * hv.z + vv.w * hv.w;
        }
        shG[bb][r] = acc;
    }
    __syncthreads();

    // ---- stage 3: M_b[a,k] = sum_c U[a,c]*F[c,k] + T[a,c]*G_b[c,k] ----
    for (int i = tid; i < PB * AD * DKK; i += 256) {
        const int bb = i / (AD * DKK);
        const int rem = i - bb * (AD * DKK);
        const int a = rem / DKK, k = rem - a * DKK;
        float m = 0.f;
#pragma unroll
        for (int c = 0; c < DCH; c++)
            m += U_w[a * DCH + c] * F_w[c * DKK + k]
               + T_w[a * DCH + c] * shG[bb][c * DKK + k];
        g_M[(b0 + bb) * AD * MROW + a * MROW + k] = m;
    }
    for (int i = tid; i < PB * AD; i += 256) {
        const int bb = i / AD, a = i - bb * AD;
        float* Mb = g_M + (b0 + bb) * AD * MROW + a * MROW;
        Mb[21] = v_w[a]; Mb[22] = T_b[a]; Mb[23] = 0.f;
    }
}

// ---------------------------------------------------------------------------
// Main (reverted to R2 scalar form): per block = one batch row; each thread
// computes 4 consecutive t.
// ---------------------------------------------------------------------------
#define TAP(mc, k) { z0 += (mc) * w[(k)];     z1 += (mc) * w[(k) + 1]; \
                     z2 += (mc) * w[(k) + 2]; z3 += (mc) * w[(k) + 3]; }

__global__ __launch_bounds__(512, 2) void dca_main_kernel(
    const float* __restrict__ alignment, const float* __restrict__ P,
    float* __restrict__ out)
{
    __shared__ float sal[TT + 20];
    __shared__ float sw[AD * MROW];
    __shared__ float sp[PLL];
    __shared__ float red[16];

    const int b = blockIdx.x, tid = threadIdx.x;

    for (int i = tid; i < TT; i += 512) sal[10 + i] = alignment[b * TT + i];
    if (tid < 10) { sal[tid] = 0.f; sal[TT + 10 + tid] = 0.f; }
    for (int i = tid; i < AD * MROW; i += 512) sw[i] = g_M[b * AD * MROW + i];
    if (tid < PLL) sp[tid] = P[tid];
    __syncthreads();

    const int t0 = tid * 4;
    float w[24];
#pragma unroll
    for (int k = 0; k < 24; k++) w[k] = sal[t0 + k];

    float e0 = 0.f, e1 = 0.f, e2 = 0.f, e3 = 0.f;

#pragma unroll 1
    for (int a = 0; a < AD; a++) {
        const float4* wp = (const float4*)(sw + a * MROW);
        float z0 = 0.f, z1 = 0.f, z2 = 0.f, z3 = 0.f;
        float4 m;
        m = wp[0]; TAP(m.x, 0)  TAP(m.y, 1)  TAP(m.z, 2)  TAP(m.w, 3)
        m = wp[1]; TAP(m.x, 4)  TAP(m.y, 5)  TAP(m.z, 6)  TAP(m.w, 7)
        m = wp[2]; TAP(m.x, 8)  TAP(m.y, 9)  TAP(m.z, 10) TAP(m.w, 11)
        m = wp[3]; TAP(m.x, 12) TAP(m.y, 13) TAP(m.z, 14) TAP(m.w, 15)
        m = wp[4]; TAP(m.x, 16) TAP(m.y, 17) TAP(m.z, 18) TAP(m.w, 19)
        m = wp[5]; TAP(m.x, 20)
        const float v = m.y, tb = m.z;
        e0 += v * tanh_fast(z0 + tb);
        e1 += v * tanh_fast(z1 + tb);
        e2 += v * tanh_fast(z2 + tb);
        e3 += v * tanh_fast(z3 + tb);
    }

    // prior: p_j = log(clip(sum_{k<11} w[j+k]*P[k], 1e-6))
    {
        float s0 = 0.f, s1 = 0.f, s2 = 0.f, s3 = 0.f;
#pragma unroll
        for (int k = 0; k < PLL; k++) {
            const float pk = sp[k];
            s0 += pk * w[k];     s1 += pk * w[k + 1];
            s2 += pk * w[k + 2]; s3 += pk * w[k + 3];
        }
        e0 += __logf(fmaxf(s0, 1e-6f));
        e1 += __logf(fmaxf(s1, 1e-6f));
        e2 += __logf(fmaxf(s2, 1e-6f));
        e3 += __logf(fmaxf(s3, 1e-6f));
    }

    const int lane = tid & 31, wid = tid >> 5;

    // block max
    float mx = fmaxf(fmaxf(e0, e1), fmaxf(e2, e3));
#pragma unroll
    for (int o = 16; o; o >>= 1) mx = fmaxf(mx, __shfl_xor_sync(~0u, mx, o));
    if (lane == 0) red[wid] = mx;
    __syncthreads();
    mx = red[0];
#pragma unroll
    for (int i = 1; i < 16; i++) mx = fmaxf(mx, red[i]);
    __syncthreads();

    // exp + block sum
    const float x0 = __expf(e0 - mx), x1 = __expf(e1 - mx);
    const float x2 = __expf(e2 - mx), x3 = __expf(e3 - mx);
    float sm = (x0 + x1) + (x2 + x3);
#pragma unroll
    for (int o = 16; o; o >>= 1) sm += __shfl_xor_sync(~0u, sm, o);
    if (lane == 0) red[wid] = sm;
    __syncthreads();
    sm = red[0];
#pragma unroll
    for (int i = 1; i < 16; i++) sm += red[i];

    const float inv = 1.0f / sm;
    float* o4 = out + b * TT + t0;
    o4[0] = x0 * inv; o4[1] = x1 * inv; o4[2] = x2 * inv; o4[3] = x3 * inv;
}

extern "C" void kernel_launch(void* const* d_in, const int* in_sizes, int n_in,
                              void* d_out, int out_size)
{
    const float* query     = (const float*)d_in[0];
    const float* alignment = (const float*)d_in[1];
    const float* P         = (const float*)d_in[2];
    const float* W_w       = (const float*)d_in[3];
    const float* W_b       = (const float*)d_in[4];
    const float* V_w       = (const float*)d_in[5];
    const float* F_w       = (const float*)d_in[6];
    const float* U_w       = (const float*)d_in[7];
    const float* T_w       = (const float*)d_in[8];
    const float* T_b       = (const float*)d_in[9];
    const float* v_w       = (const float*)d_in[10];
    float* out = (float*)d_out;

    dca_prep_kernel<<<BB / PB, 256>>>(query, W_w, W_b, V_w, F_w, U_w, T_w, T_b, v_w);
    dca_main_kernel<<<BB, 512>>>(alignment, P, out);
}

// round 6
// speedup vs baseline: 1.6176x; 1.2618x over previous
#include <cuda_runtime.h>

#define BB   256
#define TT   2048
#define QD   1024
#define AD   128
#define DCH  8
#define DKK  21
#define PLL  11
#define MROW 24   // taps 0..20, [21]=v, [22]=T_b, [23]=pad

__device__ __forceinline__ float tanh_fast(float x) {
    float y;
    asm("tanh.approx.f32 %0, %1;" : "=f"(y) : "f"(x));
    return y;
}

__device__ __forceinline__ float warp_sum(float v) {
#pragma unroll
    for (int o = 16; o; o >>= 1) v += __shfl_xor_sync(~0u, v, o);
    return v;
}

#define TAP(mc, k) { z0 += (mc) * w[(k)];     z1 += (mc) * w[(k) + 1]; \
                     z2 += (mc) * w[(k) + 2]; z3 += (mc) * w[(k) + 3]; }

// ---------------------------------------------------------------------------
// Fully fused: one block per batch. Phase A computes the per-batch fused
// 128x21 kernel M_b in smem (h = tanh(qW^T+b); G = hV^T; M = UF + TG),
// phase B runs the conv + tanh + prior + in-block softmax.
// ---------------------------------------------------------------------------
__global__ __launch_bounds__(512, 2) void dca_fused_kernel(
    const float* __restrict__ query,     const float* __restrict__ alignment,
    const float* __restrict__ P,         const float* __restrict__ W_w,
    const float* __restrict__ W_b,       const float* __restrict__ V_w,
    const float* __restrict__ F_w,       const float* __restrict__ U_w,
    const float* __restrict__ T_w,       const float* __restrict__ T_b,
    const float* __restrict__ v_w,       float* __restrict__ out)
{
    __shared__ float sal[TT + 20];          // padded alignment window
    __shared__ float sw[AD * MROW];         // fused kernel M_b (+v,+T_b)
    __shared__ float shq[QD];
    __shared__ float shh[AD];
    __shared__ float shG[DCH * DKK];
    __shared__ float sp[PLL];
    __shared__ float red[16];

    const int b = blockIdx.x, tid = threadIdx.x;
    const int lane = tid & 31, wrp = tid >> 5;   // 16 warps

    // ---- loads: query, alignment, prior taps ----
    for (int i = tid; i < QD; i += 512) shq[i] = query[b * QD + i];
    for (int i = tid; i < TT; i += 512) sal[10 + i] = alignment[b * TT + i];
    if (tid < 10) { sal[tid] = 0.f; sal[TT + 10 + tid] = 0.f; }
    if (tid < PLL) sp[tid] = P[tid];
    __syncthreads();

    // ---- phase A1: h[a] = tanh(dot(q, W_w[a,:]) + W_b[a]) ----
    // 16 warps x 8 rows each, processed in pairs for load-level parallelism.
#pragma unroll 1
    for (int i = 0; i < 8; i += 2) {
        const int a0 = wrp * 8 + i, a1 = a0 + 1;
        const float4* wr0 = (const float4*)(W_w + a0 * QD);
        const float4* wr1 = (const float4*)(W_w + a1 * QD);
        float d0 = 0.f, d1 = 0.f;
#pragma unroll
        for (int j = 0; j < 8; j++) {
            const float4 qv = *(const float4*)&shq[4 * lane + 128 * j];
            const float4 w0 = wr0[lane + 32 * j];
            const float4 w1 = wr1[lane + 32 * j];
            d0 += w0.x * qv.x + w0.y * qv.y + w0.z * qv.z + w0.w * qv.w;
            d1 += w1.x * qv.x + w1.y * qv.y + w1.z * qv.z + w1.w * qv.w;
        }
        d0 = warp_sum(d0);
        d1 = warp_sum(d1);
        if (lane == 0) {
            shh[a0] = tanhf(d0 + W_b[a0]);
            shh[a1] = tanhf(d1 + W_b[a1]);
        }
    }
    __syncthreads();

    // ---- phase A2: G[r] = dot(h, V_w[r,:]), r in [0,168) ----
    for (int r = tid; r < DCH * DKK; r += 512) {
        const float4* vr = (const float4*)(V_w + r * AD);
        const float4* hr = (const float4*)shh;
        float acc = 0.f;
#pragma unroll
        for (int j = 0; j < AD / 4; j++) {
            const float4 vv = vr[j], hv = hr[j];
            acc += vv.x * hv.x + vv.y * hv.y + vv.z * hv.z + vv.w * hv.w;
        }
        shG[r] = acc;
    }
    __syncthreads();

    // ---- phase A3: M[a,k] = sum_c U[a,c]*F[c,k] + T[a,c]*G[c,k] ----
    for (int i = tid; i < AD * DKK; i += 512) {
        const int a = i / DKK, k = i - a * DKK;
        float m = 0.f;
#pragma unroll
        for (int c = 0; c < DCH; c++)
            m += U_w[a * DCH + c] * F_w[c * DKK + k]
               + T_w[a * DCH + c] * shG[c * DKK + k];
        sw[a * MROW + k] = m;
    }
    if (tid < AD) {
        sw[tid * MROW + 21] = v_w[tid];
        sw[tid * MROW + 22] = T_b[tid];
        sw[tid * MROW + 23] = 0.f;
    }
    __syncthreads();

    // ---- phase B: conv + tanh + prior, 4 consecutive t per thread ----
    const int t0 = tid * 4;
    float w[24];
#pragma unroll
    for (int k = 0; k < 24; k++) w[k] = sal[t0 + k];

    float e0 = 0.f, e1 = 0.f, e2 = 0.f, e3 = 0.f;

#pragma unroll 1
    for (int a = 0; a < AD; a++) {
        const float4* wp = (const float4*)(sw + a * MROW);
        float z0 = 0.f, z1 = 0.f, z2 = 0.f, z3 = 0.f;
        float4 m;
        m = wp[0]; TAP(m.x, 0)  TAP(m.y, 1)  TAP(m.z, 2)  TAP(m.w, 3)
        m = wp[1]; TAP(m.x, 4)  TAP(m.y, 5)  TAP(m.z, 6)  TAP(m.w, 7)
        m = wp[2]; TAP(m.x, 8)  TAP(m.y, 9)  TAP(m.z, 10) TAP(m.w, 11)
        m = wp[3]; TAP(m.x, 12) TAP(m.y, 13) TAP(m.z, 14) TAP(m.w, 15)
        m = wp[4]; TAP(m.x, 16) TAP(m.y, 17) TAP(m.z, 18) TAP(m.w, 19)
        m = wp[5]; TAP(m.x, 20)
        const float v = m.y, tb = m.z;
        e0 += v * tanh_fast(z0 + tb);
        e1 += v * tanh_fast(z1 + tb);
        e2 += v * tanh_fast(z2 + tb);
        e3 += v * tanh_fast(z3 + tb);
    }

    // prior: p_j = log(clip(sum_{k<11} w[j+k]*P[k], 1e-6))
    {
        float s0 = 0.f, s1 = 0.f, s2 = 0.f, s3 = 0.f;
#pragma unroll
        for (int k = 0; k < PLL; k++) {
            const float pk = sp[k];
            s0 += pk * w[k];     s1 += pk * w[k + 1];
            s2 += pk * w[k + 2]; s3 += pk * w[k + 3];
        }
        e0 += __logf(fmaxf(s0, 1e-6f));
        e1 += __logf(fmaxf(s1, 1e-6f));
        e2 += __logf(fmaxf(s2, 1e-6f));
        e3 += __logf(fmaxf(s3, 1e-6f));
    }

    // ---- softmax over T within the block ----
    float mx = fmaxf(fmaxf(e0, e1), fmaxf(e2, e3));
#pragma unroll
    for (int o = 16; o; o >>= 1) mx = fmaxf(mx, __shfl_xor_sync(~0u, mx, o));
    if (lane == 0) red[wrp] = mx;
    __syncthreads();
    mx = red[0];
#pragma unroll
    for (int i = 1; i < 16; i++) mx = fmaxf(mx, red[i]);
    __syncthreads();

    const float x0 = __expf(e0 - mx), x1 = __expf(e1 - mx);
    const float x2 = __expf(e2 - mx), x3 = __expf(e3 - mx);
    float sm = (x0 + x1) + (x2 + x3);
#pragma unroll
    for (int o = 16; o; o >>= 1) sm += __shfl_xor_sync(~0u, sm, o);
    if (lane == 0) red[wrp] = sm;
    __syncthreads();
    sm = red[0];
#pragma unroll
    for (int i = 1; i < 16; i++) sm += red[i];

    const float inv = 1.0f / sm;
    float* o4 = out + b * TT + t0;
    o4[0] = x0 * inv; o4[1] = x1 * inv; o4[2] = x2 * inv; o4[3] = x3 * inv;
}

extern "C" void kernel_launch(void* const* d_in, const int* in_sizes, int n_in,
                              void* d_out, int out_size)
{
    const float* query     = (const float*)d_in[0];
    const float* alignment = (const float*)d_in[1];
    const float* P         = (const float*)d_in[2];
    const float* W_w       = (const float*)d_in[3];
    const float* W_b       = (const float*)d_in[4];
    const float* V_w       = (const float*)d_in[5];
    const float* F_w       = (const float*)d_in[6];
    const float* U_w       = (const float*)d_in[7];
    const float* T_w       = (const float*)d_in[8];
    const float* T_b       = (const float*)d_in[9];
    const float* v_w       = (const float*)d_in[10];
    float* out = (float*)d_out;

    dca_fused_kernel<<<BB, 512>>>(query, alignment, P, W_w, W_b, V_w,
                                  F_w, U_w, T_w, T_b, v_w, out);
}

// round 7
// speedup vs baseline: 1.8747x; 1.1589x over previous
#include <cuda_runtime.h>
#include <cuda_fp16.h>

#define BB   256
#define TT   2048
#define QD   1024
#define AD   128
#define DCH  8
#define DKK  21
#define PLL  11
#define MH_STRIDE 24   // half2 per M row: taps 0..20, [21]=(tb,tb), [22..23]=0
#define SALN 2080      // fp32 padded alignment (10 left pad + tail zeros)
#define NPAIR 1038

__device__ __forceinline__ float warp_sum(float v) {
#pragma unroll
    for (int o = 16; o; o >>= 1) v += __shfl_xor_sync(~0u, v, o);
    return v;
}

__device__ __forceinline__ __half2 tanh2(__half2 x) {
    unsigned xi = *reinterpret_cast<unsigned*>(&x), yi;
    asm("tanh.approx.f16x2 %0, %1;" : "=r"(yi) : "r"(xi));
    return *reinterpret_cast<__half2*>(&yi);
}

// ---------------------------------------------------------------------------
// Fully fused, fp16x2 conv core. One block per batch.
// ---------------------------------------------------------------------------
__global__ __launch_bounds__(512, 2) void dca_fused_kernel(
    const float* __restrict__ query,     const float* __restrict__ alignment,
    const float* __restrict__ P,         const float* __restrict__ W_w,
    const float* __restrict__ W_b,       const float* __restrict__ V_w,
    const float* __restrict__ F_w,       const float* __restrict__ U_w,
    const float* __restrict__ T_w,       const float* __restrict__ T_b,
    const float* __restrict__ v_w,       float* __restrict__ out)
{
    __shared__ float   sal[SALN];              // fp32 padded alignment (prior)
    __shared__ __half2 pe[NPAIR];              // (sal[2j],   sal[2j+1])
    __shared__ __half2 po[NPAIR];              // (sal[2j+1], sal[2j+2])
    __shared__ __half2 mh[AD * MH_STRIDE];     // duplicated fp16 M rows
    __shared__ float   sv[AD];                 // v weights fp32
    __shared__ float   shq[QD];
    __shared__ float   shh[AD];
    __shared__ float   shG[DCH * DKK];
    __shared__ float   sp[PLL];
    __shared__ float   red[16];

    const int b = blockIdx.x, tid = threadIdx.x;
    const int lane = tid & 31, wrp = tid >> 5;   // 16 warps

    // ---- loads ----
    for (int i = tid; i < QD; i += 512) shq[i] = query[b * QD + i];
    for (int i = tid; i < TT; i += 512) sal[10 + i] = alignment[b * TT + i];
    if (tid < 10) sal[tid] = 0.f;
    for (int i = TT + 10 + tid; i < SALN; i += 512) sal[i] = 0.f;
    if (tid < PLL) sp[tid] = P[tid];
    __syncthreads();

    // ---- half2 window pair tables ----
    for (int j = tid; j < NPAIR; j += 512) {
        pe[j] = __floats2half2_rn(sal[2 * j],     sal[2 * j + 1]);
        po[j] = __floats2half2_rn(sal[2 * j + 1], sal[2 * j + 2]);
    }

    // ---- phase A1: h[a] = tanh(dot(q, W_w[a,:]) + W_b[a]) ----
#pragma unroll 1
    for (int i = 0; i < 8; i += 2) {
        const int a0 = wrp * 8 + i, a1 = a0 + 1;
        const float4* wr0 = (const float4*)(W_w + a0 * QD);
        const float4* wr1 = (const float4*)(W_w + a1 * QD);
        float d0 = 0.f, d1 = 0.f;
#pragma unroll
        for (int j = 0; j < 8; j++) {
            const float4 qv = *(const float4*)&shq[4 * lane + 128 * j];
            const float4 w0 = wr0[lane + 32 * j];
            const float4 w1 = wr1[lane + 32 * j];
            d0 += w0.x * qv.x + w0.y * qv.y + w0.z * qv.z + w0.w * qv.w;
            d1 += w1.x * qv.x + w1.y * qv.y + w1.z * qv.z + w1.w * qv.w;
        }
        d0 = warp_sum(d0);
        d1 = warp_sum(d1);
        if (lane == 0) {
            shh[a0] = tanhf(d0 + W_b[a0]);
            shh[a1] = tanhf(d1 + W_b[a1]);
        }
    }
    __syncthreads();

    // ---- phase A2: G[r] = dot(h, V_w[r,:]) ----
    for (int r = tid; r < DCH * DKK; r += 512) {
        const float4* vr = (const float4*)(V_w + r * AD);
        const float4* hr = (const float4*)shh;
        float acc = 0.f;
#pragma unroll
        for (int j = 0; j < AD / 4; j++) {
            const float4 vv = vr[j], hv = hr[j];
            acc += vv.x * hv.x + vv.y * hv.y + vv.z * hv.z + vv.w * hv.w;
        }
        shG[r] = acc;
    }
    __syncthreads();

    // ---- phase A3: M[a,k] -> duplicated half2; tb folded; v fp32 ----
    for (int i = tid; i < AD * DKK; i += 512) {
        const int a = i / DKK, k = i - a * DKK;
        float m = 0.f;
#pragma unroll
        for (int c = 0; c < DCH; c++)
            m += U_w[a * DCH + c] * F_w[c * DKK + k]
               + T_w[a * DCH + c] * shG[c * DKK + k];
        const __half hm = __float2half_rn(m);
        mh[a * MH_STRIDE + k] = __halves2half2(hm, hm);
    }
    if (tid < AD) {
        const __half htb = __float2half_rn(T_b[tid]);
        mh[tid * MH_STRIDE + 21] = __halves2half2(htb, htb);
        mh[tid * MH_STRIDE + 22] = __halves2half2(__half(0.f), __half(0.f));
        mh[tid * MH_STRIDE + 23] = __halves2half2(__half(0.f), __half(0.f));
        sv[tid] = v_w[tid];
    }
    __syncthreads();

    // ---- phase B: conv via HFMA2, 4 positions per thread ----
    const int t0 = tid * 4;   // padded start index

    // u[k] = (sal[t0+k], sal[t0+k+1]) as half2, k = 0..22
    __half2 u[23];
#pragma unroll
    for (int k = 0; k < 23; k++)
        u[k] = (k & 1) ? po[(t0 + k - 1) >> 1] : pe[(t0 + k) >> 1];

    float e0 = 0.f, e1 = 0.f, e2 = 0.f, e3 = 0.f;

#pragma unroll 1
    for (int a = 0; a < AD; a++) {
        const __half2* row = mh + a * MH_STRIDE;
        // chunk 5 first: tap20 + (tb,tb)
        const uint4 q5 = *(const uint4*)(row + 20);
        const __half2 tap20 = ((const __half2*)&q5)[0];
        const __half2 tbtb  = ((const __half2*)&q5)[1];
        __half2 acc01 = tbtb, acc23 = tbtb;
#pragma unroll
        for (int c = 0; c < 5; c++) {
            const uint4 qc = *(const uint4*)(row + 4 * c);
            const __half2* t4 = (const __half2*)&qc;
#pragma unroll
            for (int i = 0; i < 4; i++) {
                const int k = 4 * c + i;
                acc01 = __hfma2(t4[i], u[k],     acc01);
                acc23 = __hfma2(t4[i], u[k + 2], acc23);
            }
        }
        acc01 = __hfma2(tap20, u[20], acc01);
        acc23 = __hfma2(tap20, u[22], acc23);

        const float2 f01 = __half22float2(tanh2(acc01));
        const float2 f23 = __half22float2(tanh2(acc23));
        const float v = sv[a];
        e0 += v * f01.x; e1 += v * f01.y;
        e2 += v * f23.x; e3 += v * f23.y;
    }

    // ---- prior in exact fp32: p_j = log(clip(sum_{k<11} sal[t0+j+k]*P[k])) ----
    {
        float s0 = 0.f, s1 = 0.f, s2 = 0.f, s3 = 0.f;
#pragma unroll
        for (int k = 0; k < PLL; k++) {
            const float pk = sp[k];
            s0 += pk * sal[t0 + k];     s1 += pk * sal[t0 + k + 1];
            s2 += pk * sal[t0 + k + 2]; s3 += pk * sal[t0 + k + 3];
        }
        e0 += __logf(fmaxf(s0, 1e-6f));
        e1 += __logf(fmaxf(s1, 1e-6f));
        e2 += __logf(fmaxf(s2, 1e-6f));
        e3 += __logf(fmaxf(s3, 1e-6f));
    }

    // ---- softmax over T within the block ----
    float mx = fmaxf(fmaxf(e0, e1), fmaxf(e2, e3));
#pragma unroll
    for (int o = 16; o; o >>= 1) mx = fmaxf(mx, __shfl_xor_sync(~0u, mx, o));
    if (lane == 0) red[wrp] = mx;
    __syncthreads();
    mx = red[0];
#pragma unroll
    for (int i = 1; i < 16; i++) mx = fmaxf(mx, red[i]);
    __syncthreads();

    const float x0 = __expf(e0 - mx), x1 = __expf(e1 - mx);
    const float x2 = __expf(e2 - mx), x3 = __expf(e3 - mx);
    float sm = (x0 + x1) + (x2 + x3);
#pragma unroll
    for (int o = 16; o; o >>= 1) sm += __shfl_xor_sync(~0u, sm, o);
    if (lane == 0) red[wrp] = sm;
    __syncthreads();
    sm = red[0];
#pragma unroll
    for (int i = 1; i < 16; i++) sm += red[i];

    const float inv = 1.0f / sm;
    float* o4 = out + b * TT + t0;
    o4[0] = x0 * inv; o4[1] = x1 * inv; o4[2] = x2 * inv; o4[3] = x3 * inv;
}

extern "C" void kernel_launch(void* const* d_in, const int* in_sizes, int n_in,
                              void* d_out, int out_size)
{
    const float* query     = (const float*)d_in[0];
    const float* alignment = (const float*)d_in[1];
    const float* P         = (const float*)d_in[2];
    const float* W_w       = (const float*)d_in[3];
    const float* W_b       = (const float*)d_in[4];
    const float* V_w       = (const float*)d_in[5];
    const float* F_w       = (const float*)d_in[6];
    const float* U_w       = (const float*)d_in[7];
    const float* T_w       = (const float*)d_in[8];
    const float* T_b       = (const float*)d_in[9];
    const float* v_w       = (const float*)d_in[10];
    float* out = (float*)d_out;

    dca_fused_kernel<<<BB, 512>>>(query, alignment, P, W_w, W_b, V_w,
                                  F_w, U_w, T_w, T_b, v_w, out);
}